// round 13
// baseline (speedup 1.0000x reference)
#include <cuda_runtime.h>
#include <cuda_fp16.h>
#include <math.h>
#include <stdint.h>

#define H_    16
#define HID_  2048
#define T_    1024
#define B_MAX 2
#define KD_   2048
#define KDR_  8192
#define VDR_  8192
#define CS_   18752
#define COL_Q  0
#define COL_K  2048
#define COL_V  10240
#define COL_B  18432
#define COL_F1 18496

__device__ float g_cproj[B_MAX * T_ * CS_];
__device__ float g_graw [B_MAX * T_ * KD_];
__device__ float g_gate [B_MAX * T_ * KD_];
__device__ float g_qb   [B_MAX * T_ * KD_];
__device__ float g_kb   [B_MAX * T_ * KDR_];
__device__ float g_vb   [B_MAX * T_ * VDR_];
__device__ float g_dec  [B_MAX * T_ * KD_];
__device__ float g_beta [B_MAX * T_ * 64];
__device__ float g_omix [B_MAX * T_ * KD_];

__device__ __align__(16) __half g_combh[CS_ * HID_];
__device__ __align__(16) __half g_combl[CS_ * HID_];
__device__ __align__(16) __half g_wf2h[KD_ * 128];
__device__ __align__(16) __half g_wf2l[KD_ * 128];
__device__ __align__(16) __half g_wg2h[KD_ * 128];
__device__ __align__(16) __half g_wg2l[KD_ * 128];
__device__ __align__(16) __half g_woh[HID_ * KD_];
__device__ __align__(16) __half g_wol[HID_ * KD_];
__device__ __align__(16) __half g_xh[B_MAX * T_ * HID_];
__device__ __align__(16) __half g_f1g1h[B_MAX * T_ * 256];
__device__ __align__(16) __half g_aofh[B_MAX * T_ * KD_];

static __device__ __forceinline__ float sigmoidf_(float x) { return 1.f / (1.f + expf(-x)); }
static __device__ __forceinline__ float softplusf_(float x) { return (x > 20.f) ? x : log1pf(expf(x)); }

// ---------------------------- packed f32x2 helpers -------------------------
typedef unsigned long long u64;
static __device__ __forceinline__ u64 pk2(float lo, float hi) {
    u64 r; asm("mov.b64 %0, {%1, %2};" : "=l"(r) : "f"(lo), "f"(hi)); return r;
}
static __device__ __forceinline__ void upk2(u64 v, float& lo, float& hi) {
    asm("mov.b64 {%0, %1}, %2;" : "=f"(lo), "=f"(hi) : "l"(v));
}
static __device__ __forceinline__ u64 f2mul(u64 a, u64 b) {
    u64 r; asm("mul.rn.f32x2 %0, %1, %2;" : "=l"(r) : "l"(a), "l"(b)); return r;
}
static __device__ __forceinline__ u64 f2fma(u64 a, u64 b, u64 c) {
    u64 r; asm("fma.rn.f32x2 %0, %1, %2, %3;" : "=l"(r) : "l"(a), "l"(b), "l"(c)); return r;
}
static __device__ __forceinline__ u64 f2add(u64 a, u64 b) {
    u64 r; asm("add.rn.f32x2 %0, %1, %2;" : "=l"(r) : "l"(a), "l"(b)); return r;
}

// ---------------- weight split: f32 -> fp16 hi + lo (vectorized) -----------
__global__ void splitw_kernel(const float* __restrict__ in,
                              __half* __restrict__ hi, __half* __restrict__ lo, long n4)
{
    long i = (long)blockIdx.x * blockDim.x + threadIdx.x;
    if (i >= n4) return;
    float4 v = reinterpret_cast<const float4*>(in)[i];
    __half hx = __float2half_rn(v.x), hy = __float2half_rn(v.y);
    __half hz = __float2half_rn(v.z), hw = __float2half_rn(v.w);
    reinterpret_cast<__half2*>(hi)[i * 2 + 0] = __halves2half2(hx, hy);
    reinterpret_cast<__half2*>(hi)[i * 2 + 1] = __halves2half2(hz, hw);
    reinterpret_cast<__half2*>(lo)[i * 2 + 0] =
        __halves2half2(__float2half_rn(v.x - __half2float(hx)),
                       __float2half_rn(v.y - __half2float(hy)));
    reinterpret_cast<__half2*>(lo)[i * 2 + 1] =
        __halves2half2(__float2half_rn(v.z - __half2float(hz)),
                       __float2half_rn(v.w - __half2float(hw)));
}

__global__ void cvt16_kernel(const float* __restrict__ in, __half* __restrict__ out, long n4)
{
    long i = (long)blockIdx.x * blockDim.x + threadIdx.x;
    if (i >= n4) return;
    float4 v = reinterpret_cast<const float4*>(in)[i];
    reinterpret_cast<__half2*>(out)[i * 2 + 0] =
        __halves2half2(__float2half_rn(v.x), __float2half_rn(v.y));
    reinterpret_cast<__half2*>(out)[i * 2 + 1] =
        __halves2half2(__float2half_rn(v.z), __float2half_rn(v.w));
}

__global__ void cvt_f1g1_kernel(const float* __restrict__ Cp, __half* __restrict__ out, long n)
{
    long i = (long)blockIdx.x * blockDim.x + threadIdx.x;
    if (i >= n) return;
    long r = i >> 8; int c = (int)(i & 255);
    out[i] = __float2half_rn(Cp[r * CS_ + COL_F1 + c]);
}

// ============ fp16 one-sided-split GEMM: C = A @ W^T (+bias) ===============
// Grid mapping: blockIdx.x = M-tile (fast axis), blockIdx.y = N-tile.
// A wave of 148 CTAs then spans all M-tiles x ~9 N-tiles, so the W slice per
// wave (~9 MB) and all of A (8 MB) stay L2-resident; W streams from DRAM once.
#define TBM 128
#define TBN 128
#define TBK 64
#define SM_A  0
#define SM_WH 16384
#define SM_WL 32768
#define STAGE_BYTES 49152
#define NSTAGE 4
#define TG_SMEM (NSTAGE * STAGE_BYTES)

static __device__ __forceinline__ uint32_t s2u(const void* p) {
    uint32_t a;
    asm("{ .reg .u64 t; cvta.to.shared.u64 t, %1; cvt.u32.u64 %0, t; }" : "=r"(a) : "l"(p));
    return a;
}
static __device__ __forceinline__ uint32_t swaddr(int row, int colb) {
    return (uint32_t)(row * 128 + (colb ^ ((row & 7) << 4)));
}
static __device__ __forceinline__ void cp16(uint32_t s, const void* g, uint32_t bytes) {
    asm volatile("cp.async.cg.shared.global [%0], [%1], 16, %2;" :: "r"(s), "l"(g), "r"(bytes));
}
static __device__ __forceinline__ void ldsm4(uint32_t* r, uint32_t addr) {
    asm volatile("ldmatrix.sync.aligned.m8n8.x4.shared.b16 {%0,%1,%2,%3}, [%4];"
                 : "=r"(r[0]), "=r"(r[1]), "=r"(r[2]), "=r"(r[3]) : "r"(addr));
}
static __device__ __forceinline__ void mma16816(float* d, const uint32_t* a, const uint32_t* b) {
    asm volatile(
        "mma.sync.aligned.m16n8k16.row.col.f32.f16.f16.f32 "
        "{%0,%1,%2,%3}, {%4,%5,%6,%7}, {%8,%9}, {%0,%1,%2,%3};"
        : "+f"(d[0]), "+f"(d[1]), "+f"(d[2]), "+f"(d[3])
        : "r"(a[0]), "r"(a[1]), "r"(a[2]), "r"(a[3]), "r"(b[0]), "r"(b[1]));
}

static __device__ __forceinline__ void fill_stage(
    uint32_t st, const __half* __restrict__ A,
    const __half* __restrict__ Whi, const __half* __restrict__ Wlo,
    int bm, int bn, int k0, int N, int K, int lda, int tid)
{
#pragma unroll
    for (int it = 0; it < 4; it++) {
        int q = tid + it * 256;
        int row = q >> 3, c16 = q & 7;
        uint32_t so = swaddr(row, c16 * 16);
        cp16(st + SM_A + so, A + (size_t)(bm + row) * lda + k0 + c16 * 8, 16);
    }
#pragma unroll
    for (int it = 0; it < 4; it++) {
        int q = tid + it * 256;
        int row = q >> 3, c16 = q & 7;
        uint32_t so = swaddr(row, c16 * 16);
        int n = bn + row;
        uint32_t vb = (n < N) ? 16u : 0u;
        size_t go = (size_t)((n < N) ? n : 0) * K + k0 + c16 * 8;
        cp16(st + SM_WH + so, Whi + go, vb);
        cp16(st + SM_WL + so, Wlo + go, vb);
    }
    asm volatile("cp.async.commit_group;" ::: "memory");
}

__global__ void __launch_bounds__(256, 1) tgemm_kernel(
    const __half* __restrict__ A, const __half* __restrict__ Whi,
    const __half* __restrict__ Wlo, float* __restrict__ C,
    const float* __restrict__ bias, int M, int N, int K, int lda)
{
    extern __shared__ char smem[];
    const uint32_t sb = s2u(smem);
    const int tid = threadIdx.x;
    const int wid = tid >> 5;
    const int lane = tid & 31;
    const int wm = wid & 1;
    const int wn = wid >> 1;
    const int bm = blockIdx.x * TBM;     // M fast axis (L2-friendly raster)
    const int bn = blockIdx.y * TBN;
    const int chunks = K / TBK;

    float acc[4][4][4];
#pragma unroll
    for (int mi = 0; mi < 4; mi++)
#pragma unroll
        for (int ni = 0; ni < 4; ni++)
#pragma unroll
            for (int r = 0; r < 4; r++) acc[mi][ni][r] = 0.f;

    const int pfills = (chunks < NSTAGE - 1) ? chunks : (NSTAGE - 1);
    for (int s = 0; s < pfills; s++)
        fill_stage(sb + (uint32_t)s * STAGE_BYTES, A, Whi, Wlo, bm, bn, s * TBK, N, K, lda, tid);

    const int a_row = wm * 64 + (lane & 15);
    const int a_cg  = (lane >> 4) * 16;
    const int b_grp = lane >> 3;
    const int b_row = wn * 32 + ((b_grp >> 1) << 3) + (lane & 7);
    const int b_cg  = (b_grp & 1) * 16;

    for (int c = 0; c < chunks; c++) {
        int np = chunks - 1 - c; if (np > 2) np = 2;
        if (np == 2)      asm volatile("cp.async.wait_group 2;" ::: "memory");
        else if (np == 1) asm volatile("cp.async.wait_group 1;" ::: "memory");
        else              asm volatile("cp.async.wait_group 0;" ::: "memory");
        __syncthreads();

        if (c + NSTAGE - 1 < chunks)
            fill_stage(sb + (uint32_t)((c + NSTAGE - 1) % NSTAGE) * STAGE_BYTES,
                       A, Whi, Wlo, bm, bn, (c + NSTAGE - 1) * TBK, N, K, lda, tid);

        const uint32_t st = sb + (uint32_t)(c % NSTAGE) * STAGE_BYTES;
#pragma unroll
        for (int k16 = 0; k16 < 4; k16++) {
            const int kb = k16 * 32;
            uint32_t ah[4][4], bh[4][2], bl[4][2];
#pragma unroll
            for (int mi = 0; mi < 4; mi++)
                ldsm4(ah[mi], st + SM_A + swaddr(a_row + mi * 16, kb + a_cg));
#pragma unroll
            for (int p = 0; p < 2; p++) {
                uint32_t th[4], tl[4];
                uint32_t so = swaddr(b_row + p * 16, kb + b_cg);
                ldsm4(th, st + SM_WH + so);
                ldsm4(tl, st + SM_WL + so);
                bh[p * 2][0] = th[0]; bh[p * 2][1] = th[1];
                bh[p * 2 + 1][0] = th[2]; bh[p * 2 + 1][1] = th[3];
                bl[p * 2][0] = tl[0]; bl[p * 2][1] = tl[1];
                bl[p * 2 + 1][0] = tl[2]; bl[p * 2 + 1][1] = tl[3];
            }
#pragma unroll
            for (int mi = 0; mi < 4; mi++)
#pragma unroll
                for (int ni = 0; ni < 4; ni++) {
                    mma16816(acc[mi][ni], ah[mi], bh[ni]);
                    mma16816(acc[mi][ni], ah[mi], bl[ni]);
                }
        }
    }

    const int erow0 = bm + wm * 64 + (lane >> 2);
    const int ecol0 = bn + wn * 32 + (lane & 3) * 2;
#pragma unroll
    for (int mi = 0; mi < 4; mi++) {
#pragma unroll
        for (int ni = 0; ni < 4; ni++) {
            int col = ecol0 + ni * 8;
            if (col < N) {
                float b0 = bias ? bias[col] : 0.f;
                float b1 = bias ? bias[col + 1] : 0.f;
                float2 v0 = make_float2(acc[mi][ni][0] + b0, acc[mi][ni][1] + b1);
                float2 v1 = make_float2(acc[mi][ni][2] + b0, acc[mi][ni][3] + b1);
                *reinterpret_cast<float2*>(C + (size_t)(erow0 + mi * 16) * N + col) = v0;
                *reinterpret_cast<float2*>(C + (size_t)(erow0 + mi * 16 + 8) * N + col) = v1;
            }
        }
    }
}

// -------- fused causal conv + SiLU + per-128 L2 norm (q and k paths) -------
__global__ void convnorm_kernel(const float* __restrict__ Cp, const float* __restrict__ cw,
                                float* __restrict__ out, int col0, int CH, float scale, int T)
{
    const int G = CH >> 7;
    const int bt = blockIdx.x / G;
    const int grp = blockIdx.x % G;
    const int d = threadIdx.x;
    const int c = grp * 128 + d;
    const int t = bt % T;
    const float4 wv = *reinterpret_cast<const float4*>(cw + (size_t)c * 4);
    const float* ip = Cp + (size_t)bt * CS_ + col0 + c;
    float s = ip[0] * wv.w;
    if (t >= 1) s += ip[-(long)CS_] * wv.z;
    if (t >= 2) s += ip[-2L * CS_] * wv.y;
    if (t >= 3) s += ip[-3L * CS_] * wv.x;
    s = s * sigmoidf_(s);
    float ss = s * s;
#pragma unroll
    for (int off = 16; off > 0; off >>= 1) ss += __shfl_xor_sync(0xffffffffu, ss, off);
    __shared__ float ws[4];
    if ((d & 31) == 0) ws[d >> 5] = ss;
    __syncthreads();
    float tot = ws[0] + ws[1] + ws[2] + ws[3];
    out[(size_t)bt * CH + c] = s * rsqrtf(tot + 1e-6f) * scale;
}

__global__ void conv_silu_kernel(const float* __restrict__ Cp, const float* __restrict__ cw,
                                 float* __restrict__ out, int col0, int CH, long total, int T)
{
    long idx = (long)blockIdx.x * blockDim.x + threadIdx.x;
    if (idx >= total) return;
    int c = (int)(idx % CH);
    long bt = idx / CH;
    int t = (int)(bt % T);
    const float4 wv = *reinterpret_cast<const float4*>(cw + (size_t)c * 4);
    const float* ip = Cp + (size_t)bt * CS_ + col0 + c;
    float s = ip[0] * wv.w;
    if (t >= 1) s += ip[-(long)CS_] * wv.z;
    if (t >= 2) s += ip[-2L * CS_] * wv.y;
    if (t >= 3) s += ip[-3L * CS_] * wv.x;
    out[idx] = s * sigmoidf_(s);
}

__global__ void decay_kernel(const float* __restrict__ graw, const float* __restrict__ dt_bias,
                             const float* __restrict__ A_log, float* __restrict__ dec, long total)
{
    long idx = (long)blockIdx.x * blockDim.x + threadIdx.x;
    if (idx >= total) return;
    int ch = (int)(idx & 2047);
    int h = ch >> 7;
    float x = graw[idx] + dt_bias[ch];
    dec[idx] = expf(-expf(A_log[h]) * softplusf_(x));
}

__global__ void beta_kernel(const float* __restrict__ Cp, float* __restrict__ out, long total)
{
    long idx = (long)blockIdx.x * blockDim.x + threadIdx.x;
    if (idx >= total) return;
    long bt = idx >> 6; int c = (int)(idx & 63);
    out[idx] = sigmoidf_(Cp[bt * CS_ + COL_B + c]);
}

// ----------------- delta-rule microscan (packed f32x2 FFMA2) ---------------
__global__ void __launch_bounds__(128, 1) scan_kernel(
    const float* __restrict__ qp, const float* __restrict__ kp,
    const float* __restrict__ vp, const float* __restrict__ dec,
    const float* __restrict__ beta,
    const float* __restrict__ dt_bias, const float* __restrict__ A_log,
    const float* __restrict__ micro_logits,
    float* __restrict__ o_mix, int T)
{
    const int split = blockIdx.x;
    const int h = blockIdx.y;
    const int b = blockIdx.z;
    const int tid = threadIdx.x;
    const int w = tid >> 5;
    const int c = tid & 31;
    const int vcol = split * 32 + c;

    __shared__ __align__(8) float sq[128], sdec[128], sk[512], sv[512];
    __shared__ float red[2][128], ored[128], sb4[4];

    const float A = expf(A_log[h]);
    u64 sdf2[16], swm2[4];
#pragma unroll
    for (int i = 0; i < 16; i++) {
        int d0 = w * 32 + 2 * i;
        float f0 = expf(-A * softplusf_(-10000.0f + dt_bias[h * 128 + d0]));
        float f1 = expf(-A * softplusf_(-10000.0f + dt_bias[h * 128 + d0 + 1]));
        sdf2[i] = pk2(f0, f1);
    }
    {
        float m0 = micro_logits[h * 4 + 0], m1 = micro_logits[h * 4 + 1];
        float m2 = micro_logits[h * 4 + 2], m3 = micro_logits[h * 4 + 3];
        float mx = fmaxf(fmaxf(m0, m1), fmaxf(m2, m3));
        float e0 = expf(m0 - mx), e1 = expf(m1 - mx), e2 = expf(m2 - mx), e3 = expf(m3 - mx);
        float inv = 1.f / (e0 + e1 + e2 + e3);
        swm2[0] = pk2(e0 * inv, e0 * inv); swm2[1] = pk2(e1 * inv, e1 * inv);
        swm2[2] = pk2(e2 * inv, e2 * inv); swm2[3] = pk2(e3 * inv, e3 * inv);
    }

    u64 S2[16];
#pragma unroll
    for (int i = 0; i < 16; i++) S2[i] = pk2(0.f, 0.f);

    {
        size_t base0 = ((size_t)(b * T) * H_ + h);
        size_t q0 = base0 * 128, k0 = base0 * 512;
#pragma unroll
        for (int i = 0; i < 5; i++) {
            int fl = tid + i * 128;
            const float2* src;
            float2* dst;
            if (fl < 64)       { src = (const float2*)(qp  + q0) + fl;        dst = (float2*)sq   + fl; }
            else if (fl < 128) { src = (const float2*)(dec + q0) + (fl - 64); dst = (float2*)sdec + (fl - 64); }
            else if (fl < 384) { src = (const float2*)(kp  + k0) + (fl - 128);dst = (float2*)sk   + (fl - 128); }
            else               { src = (const float2*)(vp  + k0) + (fl - 384);dst = (float2*)sv   + (fl - 384); }
            *dst = *src;
        }
        if (tid < 4) sb4[tid] = beta[base0 * 4 + tid];
    }
    __syncthreads();

    for (int t = 0; t < T; t++) {
        float2 pf[5]; float pfb = 0.f;
        {
            int tn = (t + 1 < T) ? (t + 1) : t;
            size_t basen = ((size_t)(b * T + tn) * H_ + h);
            size_t qn = basen * 128, kn = basen * 512;
#pragma unroll
            for (int i = 0; i < 5; i++) {
                int fl = tid + i * 128;
                const float2* src;
                if (fl < 64)       src = (const float2*)(qp  + qn) + fl;
                else if (fl < 128) src = (const float2*)(dec + qn) + (fl - 64);
                else if (fl < 384) src = (const float2*)(kp  + kn) + (fl - 128);
                else               src = (const float2*)(vp  + kn) + (fl - 384);
                pf[i] = *src;
            }
            if (tid < 4) pfb = beta[basen * 4 + tid];
        }

        u64 q2[16];
        {
            const float2* qsp = (const float2*)sq + w * 16;
#pragma unroll
            for (int i = 0; i < 16; i++) { float2 v = qsp[i]; q2[i] = pk2(v.x, v.y); }
        }

        u64 oacc2 = pk2(0.f, 0.f);
#pragma unroll
        for (int j = 0; j < 4; j++) {
            const float2* ksp = (const float2*)(sk + j * 128) + w * 16;
            u64 k2[16];
#pragma unroll
            for (int i = 0; i < 16; i++) { float2 v = ksp[i]; k2[i] = pk2(v.x, v.y); }

            u64 ua = pk2(0.f, 0.f), ub = pk2(0.f, 0.f);
            if (j == 0) {
                const float2* dsp = (const float2*)sdec + w * 16;
#pragma unroll
                for (int i = 0; i < 16; i++) {
                    float2 dv = dsp[i];
                    S2[i] = f2mul(S2[i], pk2(dv.x, dv.y));
                    if (i & 1) ub = f2fma(k2[i], S2[i], ub);
                    else       ua = f2fma(k2[i], S2[i], ua);
                }
            } else {
#pragma unroll
                for (int i = 0; i < 16; i++) {
                    S2[i] = f2mul(S2[i], sdf2[i]);
                    if (i & 1) ub = f2fma(k2[i], S2[i], ub);
                    else       ua = f2fma(k2[i], S2[i], ua);
                }
            }
            float ux, uy; upk2(f2add(ua, ub), ux, uy);
            red[j & 1][tid] = ux + uy;
            __syncthreads();
            float u = red[j & 1][c] + red[j & 1][32 + c] + red[j & 1][64 + c] + red[j & 1][96 + c];
            float coef = sb4[j] * (sv[j * 128 + vcol] - u);
            u64 c2 = pk2(coef, coef);

            u64 da = pk2(0.f, 0.f), db = pk2(0.f, 0.f);
#pragma unroll
            for (int i = 0; i < 16; i++) {
                S2[i] = f2fma(c2, k2[i], S2[i]);
                if (i & 1) db = f2fma(q2[i], S2[i], db);
                else       da = f2fma(q2[i], S2[i], da);
            }
            oacc2 = f2fma(swm2[j], f2add(da, db), oacc2);
        }

        float ox, oy; upk2(oacc2, ox, oy);
        ored[tid] = ox + oy;
        __syncthreads();
        if (w == 0)
            o_mix[((size_t)(b * T + t) * H_ + h) * 128 + vcol] =
                ored[c] + ored[32 + c] + ored[64 + c] + ored[96 + c];
#pragma unroll
        for (int i = 0; i < 5; i++) {
            int fl = tid + i * 128;
            float2* dst;
            if (fl < 64)       dst = (float2*)sq   + fl;
            else if (fl < 128) dst = (float2*)sdec + (fl - 64);
            else if (fl < 384) dst = (float2*)sk   + (fl - 128);
            else               dst = (float2*)sv   + (fl - 384);
            *dst = pf[i];
        }
        if (tid < 4) sb4[tid] = pfb;
        __syncthreads();
    }
}

// ------- output norm * gate -> fp16 (feeds o_proj GEMM directly) -----------
__global__ void post_kernel(const float* __restrict__ omix, const float* __restrict__ gate,
                            const float* __restrict__ onw, __half* __restrict__ ofin)
{
    size_t row = blockIdx.x;
    int v = threadIdx.x;
    float o = omix[row * 128 + v];
    float s = o * o;
#pragma unroll
    for (int off = 16; off > 0; off >>= 1) s += __shfl_xor_sync(0xffffffffu, s, off);
    __shared__ float ws[4];
    if ((v & 31) == 0) ws[v >> 5] = s;
    __syncthreads();
    float mean = (ws[0] + ws[1] + ws[2] + ws[3]) * (1.f / 128.f);
    float r = o * rsqrtf(mean + 1e-5f) * onw[v] * sigmoidf_(gate[row * 128 + v]);
    ofin[row * 128 + v] = __float2half_rn(r);
}

// ---------------------------------------------------------------------------
extern "C" void kernel_launch(void* const* d_in, const int* in_sizes, int n_in,
                              void* d_out, int out_size)
{
    const float* x       = (const float*)d_in[0];
    const float* q_proj  = (const float*)d_in[1];
    const float* k_proj  = (const float*)d_in[2];
    const float* v_proj  = (const float*)d_in[3];
    const float* q_convw = (const float*)d_in[4];
    const float* k_convw = (const float*)d_in[5];
    const float* v_convw = (const float*)d_in[6];
    const float* f1_w    = (const float*)d_in[7];
    const float* f2_w    = (const float*)d_in[8];
    const float* b_proj  = (const float*)d_in[9];
    const float* micro   = (const float*)d_in[10];
    const float* A_log   = (const float*)d_in[11];
    const float* dt_bias = (const float*)d_in[12];
    const float* g1_w    = (const float*)d_in[13];
    const float* g2_w    = (const float*)d_in[14];
    const float* g2_b    = (const float*)d_in[15];
    const float* o_normw = (const float*)d_in[16];
    const float* o_proj  = (const float*)d_in[17];
    float* out = (float*)d_out;

    const int T = T_;
    const int BT = in_sizes[0] / HID_;
    const int B = BT / T;

    cudaFuncSetAttribute(tgemm_kernel, cudaFuncAttributeMaxDynamicSharedMemorySize, TG_SMEM);

    float *cproj, *graw, *gate, *qb, *kb, *vb, *decb, *betab, *omix;
    cudaGetSymbolAddress((void**)&cproj, g_cproj);
    cudaGetSymbolAddress((void**)&graw,  g_graw);
    cudaGetSymbolAddress((void**)&gate,  g_gate);
    cudaGetSymbolAddress((void**)&qb,    g_qb);
    cudaGetSymbolAddress((void**)&kb,    g_kb);
    cudaGetSymbolAddress((void**)&vb,    g_vb);
    cudaGetSymbolAddress((void**)&decb,  g_dec);
    cudaGetSymbolAddress((void**)&betab, g_beta);
    cudaGetSymbolAddress((void**)&omix,  g_omix);

    __half *combh, *combl, *f2h, *f2l, *g2h, *g2l, *woh, *wol, *xh, *f1g1h, *aofh;
    cudaGetSymbolAddress((void**)&combh, g_combh);
    cudaGetSymbolAddress((void**)&combl, g_combl);
    cudaGetSymbolAddress((void**)&f2h,   g_wf2h);
    cudaGetSymbolAddress((void**)&f2l,   g_wf2l);
    cudaGetSymbolAddress((void**)&g2h,   g_wg2h);
    cudaGetSymbolAddress((void**)&g2l,   g_wg2l);
    cudaGetSymbolAddress((void**)&woh,   g_woh);
    cudaGetSymbolAddress((void**)&wol,   g_wol);
    cudaGetSymbolAddress((void**)&xh,    g_xh);
    cudaGetSymbolAddress((void**)&f1g1h, g_f1g1h);
    cudaGetSymbolAddress((void**)&aofh,  g_aofh);

    auto g4 = [](long n4) { return (unsigned)((n4 + 255) / 256); };

    splitw_kernel<<<g4((long)KD_  * HID_ / 4), 256>>>(q_proj, combh,                combl,                (long)KD_  * HID_ / 4);
    splitw_kernel<<<g4((long)KDR_ * HID_ / 4), 256>>>(k_proj, combh + (long)COL_K  * HID_, combl + (long)COL_K  * HID_, (long)KDR_ * HID_ / 4);
    splitw_kernel<<<g4((long)VDR_ * HID_ / 4), 256>>>(v_proj, combh + (long)COL_V  * HID_, combl + (long)COL_V  * HID_, (long)VDR_ * HID_ / 4);
    splitw_kernel<<<g4((long)64   * HID_ / 4), 256>>>(b_proj, combh + (long)COL_B  * HID_, combl + (long)COL_B  * HID_, (long)64   * HID_ / 4);
    splitw_kernel<<<g4((long)128  * HID_ / 4), 256>>>(f1_w,   combh + (long)COL_F1 * HID_, combl + (long)COL_F1 * HID_, (long)128  * HID_ / 4);
    splitw_kernel<<<g4((long)128  * HID_ / 4), 256>>>(g1_w,   combh + (long)(COL_F1 + 128) * HID_, combl + (long)(COL_F1 + 128) * HID_, (long)128 * HID_ / 4);
    splitw_kernel<<<g4((long)KD_ * 128 / 4),  256>>>(f2_w, f2h, f2l, (long)KD_ * 128 / 4);
    splitw_kernel<<<g4((long)KD_ * 128 / 4),  256>>>(g2_w, g2h, g2l, (long)KD_ * 128 / 4);
    splitw_kernel<<<g4((long)HID_ * KD_ / 4), 256>>>(o_proj, woh, wol, (long)HID_ * KD_ / 4);
    cvt16_kernel<<<g4((long)BT * HID_ / 4), 256>>>(x, xh, (long)BT * HID_ / 4);

    auto tg = [&](const __half* a, const __half* wh, const __half* wl,
                  float* C, const float* bias, int M, int N, int K, int lda) {
        dim3 grid((unsigned)(M / TBM), (unsigned)((N + TBN - 1) / TBN));  // M fast
        tgemm_kernel<<<grid, 256, TG_SMEM>>>(a, wh, wl, C, bias, M, N, K, lda);
    };

    // merged projection GEMM (q|k|v|b|f1|g1)
    tg(xh, combh, combl, cproj, nullptr, BT, CS_, HID_, HID_);

    // low-rank expansions off f1/g1 (K=128)
    cvt_f1g1_kernel<<<g4((long)BT * 256), 256>>>(cproj, f1g1h, (long)BT * 256);
    tg(f1g1h,       f2h, f2l, graw, nullptr, BT, KD_, 128, 256);
    tg(f1g1h + 128, g2h, g2l, gate, g2_b,    BT, KD_, 128, 256);

    // conv+silu(+l2norm) from merged proj
    convnorm_kernel<<<(unsigned)(BT * (KD_ >> 7)),  128>>>(cproj, q_convw, qb, COL_Q, KD_,  0.08838834764831843f, T);
    convnorm_kernel<<<(unsigned)(BT * (KDR_ >> 7)), 128>>>(cproj, k_convw, kb, COL_K, KDR_, 1.0f, T);
    long nv = (long)BT * VDR_;
    conv_silu_kernel<<<(unsigned)((nv + 255) / 256), 256>>>(cproj, v_convw, vb, COL_V, VDR_, nv, T);

    long nq = (long)BT * KD_;
    decay_kernel<<<(unsigned)((nq + 255) / 256), 256>>>(graw, dt_bias, A_log, decb, nq);
    long nb = (long)BT * 64;
    beta_kernel<<<(unsigned)((nb + 255) / 256), 256>>>(cproj, betab, nb);

    // sequential microscan (packed f32x2)
    dim3 sgrid(4, H_, (unsigned)B);
    scan_kernel<<<sgrid, 128>>>(qb, kb, vb, decb, betab, dt_bias, A_log, micro, omix, T);

    // output norm + gate -> fp16, then o_proj
    post_kernel<<<(unsigned)(BT * H_), 128>>>(omix, gate, o_normw, aofh);
    tg(aofh, woh, wol, out, nullptr, BT, HID_, KD_, KD_);
}

// round 14
// speedup vs baseline: 1.0485x; 1.0485x over previous
#include <cuda_runtime.h>
#include <cuda_fp16.h>
#include <math.h>
#include <stdint.h>

#define H_    16
#define HID_  2048
#define T_    1024
#define B_MAX 2
#define KD_   2048
#define KDR_  8192
#define VDR_  8192
#define CS_   18752
#define COL_Q  0
#define COL_K  2048
#define COL_V  10240
#define COL_B  18432
#define COL_F1 18496

__device__ float g_cproj[B_MAX * T_ * CS_];
__device__ float g_graw [B_MAX * T_ * KD_];
__device__ float g_gate [B_MAX * T_ * KD_];
__device__ float g_qb   [B_MAX * T_ * KD_];
__device__ float g_kb   [B_MAX * T_ * KDR_];
__device__ float g_vb   [B_MAX * T_ * VDR_];
__device__ float g_dec  [B_MAX * T_ * KD_];
__device__ float g_beta [B_MAX * T_ * 64];
__device__ float g_omix [B_MAX * T_ * KD_];

__device__ __align__(16) __half g_combh[CS_ * HID_];
__device__ __align__(16) __half g_combl[CS_ * HID_];
__device__ __align__(16) __half g_wf2h[KD_ * 128];
__device__ __align__(16) __half g_wf2l[KD_ * 128];
__device__ __align__(16) __half g_wg2h[KD_ * 128];
__device__ __align__(16) __half g_wg2l[KD_ * 128];
__device__ __align__(16) __half g_woh[HID_ * KD_];
__device__ __align__(16) __half g_wol[HID_ * KD_];
__device__ __align__(16) __half g_xh[B_MAX * T_ * HID_];
__device__ __align__(16) __half g_f1g1h[B_MAX * T_ * 256];
__device__ __align__(16) __half g_aofh[B_MAX * T_ * KD_];

static __device__ __forceinline__ float sigmoidf_(float x) { return 1.f / (1.f + expf(-x)); }
static __device__ __forceinline__ float softplusf_(float x) { return (x > 20.f) ? x : log1pf(expf(x)); }

// ---------------------------- packed f32x2 helpers -------------------------
typedef unsigned long long u64;
static __device__ __forceinline__ u64 pk2(float lo, float hi) {
    u64 r; asm("mov.b64 %0, {%1, %2};" : "=l"(r) : "f"(lo), "f"(hi)); return r;
}
static __device__ __forceinline__ void upk2(u64 v, float& lo, float& hi) {
    asm("mov.b64 {%0, %1}, %2;" : "=f"(lo), "=f"(hi) : "l"(v));
}
static __device__ __forceinline__ u64 f2mul(u64 a, u64 b) {
    u64 r; asm("mul.rn.f32x2 %0, %1, %2;" : "=l"(r) : "l"(a), "l"(b)); return r;
}
static __device__ __forceinline__ u64 f2fma(u64 a, u64 b, u64 c) {
    u64 r; asm("fma.rn.f32x2 %0, %1, %2, %3;" : "=l"(r) : "l"(a), "l"(b), "l"(c)); return r;
}
static __device__ __forceinline__ u64 f2add(u64 a, u64 b) {
    u64 r; asm("add.rn.f32x2 %0, %1, %2;" : "=l"(r) : "l"(a), "l"(b)); return r;
}

// ---------------- weight split: f32 -> fp16 hi + lo (vectorized) -----------
__global__ void splitw_kernel(const float* __restrict__ in,
                              __half* __restrict__ hi, __half* __restrict__ lo, long n4)
{
    long i = (long)blockIdx.x * blockDim.x + threadIdx.x;
    if (i >= n4) return;
    float4 v = reinterpret_cast<const float4*>(in)[i];
    __half hx = __float2half_rn(v.x), hy = __float2half_rn(v.y);
    __half hz = __float2half_rn(v.z), hw = __float2half_rn(v.w);
    reinterpret_cast<__half2*>(hi)[i * 2 + 0] = __halves2half2(hx, hy);
    reinterpret_cast<__half2*>(hi)[i * 2 + 1] = __halves2half2(hz, hw);
    reinterpret_cast<__half2*>(lo)[i * 2 + 0] =
        __halves2half2(__float2half_rn(v.x - __half2float(hx)),
                       __float2half_rn(v.y - __half2float(hy)));
    reinterpret_cast<__half2*>(lo)[i * 2 + 1] =
        __halves2half2(__float2half_rn(v.z - __half2float(hz)),
                       __float2half_rn(v.w - __half2float(hw)));
}

__global__ void cvt16_kernel(const float* __restrict__ in, __half* __restrict__ out, long n4)
{
    long i = (long)blockIdx.x * blockDim.x + threadIdx.x;
    if (i >= n4) return;
    float4 v = reinterpret_cast<const float4*>(in)[i];
    reinterpret_cast<__half2*>(out)[i * 2 + 0] =
        __halves2half2(__float2half_rn(v.x), __float2half_rn(v.y));
    reinterpret_cast<__half2*>(out)[i * 2 + 1] =
        __halves2half2(__float2half_rn(v.z), __float2half_rn(v.w));
}

__global__ void cvt_f1g1_kernel(const float* __restrict__ Cp, __half* __restrict__ out, long n)
{
    long i = (long)blockIdx.x * blockDim.x + threadIdx.x;
    if (i >= n) return;
    long r = i >> 8; int c = (int)(i & 255);
    out[i] = __float2half_rn(Cp[r * CS_ + COL_F1 + c]);
}

// ============ fp16 one-sided-split GEMM: C = A @ W^T (+bias) ===============
// Double-buffered (2 stages, 96 KB) so TWO CTAs co-reside per SM -> 16 warps,
// hiding ldsm/mma latency that a single 8-warp CTA exposes.
#define TBM 128
#define TBN 128
#define TBK 64
#define SM_A  0
#define SM_WH 16384
#define SM_WL 32768
#define STAGE_BYTES 49152
#define NSTAGE 2
#define TG_SMEM (NSTAGE * STAGE_BYTES)

static __device__ __forceinline__ uint32_t s2u(const void* p) {
    uint32_t a;
    asm("{ .reg .u64 t; cvta.to.shared.u64 t, %1; cvt.u32.u64 %0, t; }" : "=r"(a) : "l"(p));
    return a;
}
static __device__ __forceinline__ uint32_t swaddr(int row, int colb) {
    return (uint32_t)(row * 128 + (colb ^ ((row & 7) << 4)));
}
static __device__ __forceinline__ void cp16(uint32_t s, const void* g, uint32_t bytes) {
    asm volatile("cp.async.cg.shared.global [%0], [%1], 16, %2;" :: "r"(s), "l"(g), "r"(bytes));
}
static __device__ __forceinline__ void ldsm4(uint32_t* r, uint32_t addr) {
    asm volatile("ldmatrix.sync.aligned.m8n8.x4.shared.b16 {%0,%1,%2,%3}, [%4];"
                 : "=r"(r[0]), "=r"(r[1]), "=r"(r[2]), "=r"(r[3]) : "r"(addr));
}
static __device__ __forceinline__ void mma16816(float* d, const uint32_t* a, const uint32_t* b) {
    asm volatile(
        "mma.sync.aligned.m16n8k16.row.col.f32.f16.f16.f32 "
        "{%0,%1,%2,%3}, {%4,%5,%6,%7}, {%8,%9}, {%0,%1,%2,%3};"
        : "+f"(d[0]), "+f"(d[1]), "+f"(d[2]), "+f"(d[3])
        : "r"(a[0]), "r"(a[1]), "r"(a[2]), "r"(a[3]), "r"(b[0]), "r"(b[1]));
}

static __device__ __forceinline__ void fill_stage(
    uint32_t st, const __half* __restrict__ A,
    const __half* __restrict__ Whi, const __half* __restrict__ Wlo,
    int bm, int bn, int k0, int N, int K, int lda, int tid)
{
#pragma unroll
    for (int it = 0; it < 4; it++) {
        int q = tid + it * 256;
        int row = q >> 3, c16 = q & 7;
        uint32_t so = swaddr(row, c16 * 16);
        cp16(st + SM_A + so, A + (size_t)(bm + row) * lda + k0 + c16 * 8, 16);
    }
#pragma unroll
    for (int it = 0; it < 4; it++) {
        int q = tid + it * 256;
        int row = q >> 3, c16 = q & 7;
        uint32_t so = swaddr(row, c16 * 16);
        int n = bn + row;
        uint32_t vb = (n < N) ? 16u : 0u;
        size_t go = (size_t)((n < N) ? n : 0) * K + k0 + c16 * 8;
        cp16(st + SM_WH + so, Whi + go, vb);
        cp16(st + SM_WL + so, Wlo + go, vb);
    }
    asm volatile("cp.async.commit_group;" ::: "memory");
}

__global__ void __launch_bounds__(256, 2) tgemm_kernel(
    const __half* __restrict__ A, const __half* __restrict__ Whi,
    const __half* __restrict__ Wlo, float* __restrict__ C,
    const float* __restrict__ bias, int M, int N, int K, int lda)
{
    extern __shared__ char smem[];
    const uint32_t sb = s2u(smem);
    const int tid = threadIdx.x;
    const int wid = tid >> 5;
    const int lane = tid & 31;
    const int wm = wid & 1;
    const int wn = wid >> 1;
    const int bm = blockIdx.x * TBM;
    const int bn = blockIdx.y * TBN;
    const int chunks = K / TBK;

    float acc[4][4][4];
#pragma unroll
    for (int mi = 0; mi < 4; mi++)
#pragma unroll
        for (int ni = 0; ni < 4; ni++)
#pragma unroll
            for (int r = 0; r < 4; r++) acc[mi][ni][r] = 0.f;

    const int pfills = (chunks < NSTAGE) ? chunks : NSTAGE;
    for (int s = 0; s < pfills; s++)
        fill_stage(sb + (uint32_t)s * STAGE_BYTES, A, Whi, Wlo, bm, bn, s * TBK, N, K, lda, tid);

    const int a_row = wm * 64 + (lane & 15);
    const int a_cg  = (lane >> 4) * 16;
    const int b_grp = lane >> 3;
    const int b_row = wn * 32 + ((b_grp >> 1) << 3) + (lane & 7);
    const int b_cg  = (b_grp & 1) * 16;

    for (int c = 0; c < chunks; c++) {
        if (c + 1 < chunks) asm volatile("cp.async.wait_group 1;" ::: "memory");
        else                asm volatile("cp.async.wait_group 0;" ::: "memory");
        __syncthreads();

        const uint32_t st = sb + (uint32_t)(c & 1) * STAGE_BYTES;
#pragma unroll
        for (int k16 = 0; k16 < 4; k16++) {
            const int kb = k16 * 32;
            uint32_t ah[4][4], bh[4][2], bl[4][2];
#pragma unroll
            for (int mi = 0; mi < 4; mi++)
                ldsm4(ah[mi], st + SM_A + swaddr(a_row + mi * 16, kb + a_cg));
#pragma unroll
            for (int p = 0; p < 2; p++) {
                uint32_t th[4], tl[4];
                uint32_t so = swaddr(b_row + p * 16, kb + b_cg);
                ldsm4(th, st + SM_WH + so);
                ldsm4(tl, st + SM_WL + so);
                bh[p * 2][0] = th[0]; bh[p * 2][1] = th[1];
                bh[p * 2 + 1][0] = th[2]; bh[p * 2 + 1][1] = th[3];
                bl[p * 2][0] = tl[0]; bl[p * 2][1] = tl[1];
                bl[p * 2 + 1][0] = tl[2]; bl[p * 2 + 1][1] = tl[3];
            }
#pragma unroll
            for (int mi = 0; mi < 4; mi++)
#pragma unroll
                for (int ni = 0; ni < 4; ni++) {
                    mma16816(acc[mi][ni], ah[mi], bh[ni]);
                    mma16816(acc[mi][ni], ah[mi], bl[ni]);
                }
        }

        if (c + 2 < chunks) {
            __syncthreads();   // stage (c&1) fully consumed by all warps
            fill_stage(sb + (uint32_t)(c & 1) * STAGE_BYTES,
                       A, Whi, Wlo, bm, bn, (c + 2) * TBK, N, K, lda, tid);
        }
    }

    const int erow0 = bm + wm * 64 + (lane >> 2);
    const int ecol0 = bn + wn * 32 + (lane & 3) * 2;
#pragma unroll
    for (int mi = 0; mi < 4; mi++) {
#pragma unroll
        for (int ni = 0; ni < 4; ni++) {
            int col = ecol0 + ni * 8;
            if (col < N) {
                float b0 = bias ? bias[col] : 0.f;
                float b1 = bias ? bias[col + 1] : 0.f;
                float2 v0 = make_float2(acc[mi][ni][0] + b0, acc[mi][ni][1] + b1);
                float2 v1 = make_float2(acc[mi][ni][2] + b0, acc[mi][ni][3] + b1);
                *reinterpret_cast<float2*>(C + (size_t)(erow0 + mi * 16) * N + col) = v0;
                *reinterpret_cast<float2*>(C + (size_t)(erow0 + mi * 16 + 8) * N + col) = v1;
            }
        }
    }
}

// -------- fused causal conv + SiLU + per-128 L2 norm (q and k paths) -------
__global__ void convnorm_kernel(const float* __restrict__ Cp, const float* __restrict__ cw,
                                float* __restrict__ out, int col0, int CH, float scale, int T)
{
    const int G = CH >> 7;
    const int bt = blockIdx.x / G;
    const int grp = blockIdx.x % G;
    const int d = threadIdx.x;
    const int c = grp * 128 + d;
    const int t = bt % T;
    const float4 wv = *reinterpret_cast<const float4*>(cw + (size_t)c * 4);
    const float* ip = Cp + (size_t)bt * CS_ + col0 + c;
    float s = ip[0] * wv.w;
    if (t >= 1) s += ip[-(long)CS_] * wv.z;
    if (t >= 2) s += ip[-2L * CS_] * wv.y;
    if (t >= 3) s += ip[-3L * CS_] * wv.x;
    s = s * sigmoidf_(s);
    float ss = s * s;
#pragma unroll
    for (int off = 16; off > 0; off >>= 1) ss += __shfl_xor_sync(0xffffffffu, ss, off);
    __shared__ float ws[4];
    if ((d & 31) == 0) ws[d >> 5] = ss;
    __syncthreads();
    float tot = ws[0] + ws[1] + ws[2] + ws[3];
    out[(size_t)bt * CH + c] = s * rsqrtf(tot + 1e-6f) * scale;
}

__global__ void conv_silu_kernel(const float* __restrict__ Cp, const float* __restrict__ cw,
                                 float* __restrict__ out, int col0, int CH, long total, int T)
{
    long idx = (long)blockIdx.x * blockDim.x + threadIdx.x;
    if (idx >= total) return;
    int c = (int)(idx % CH);
    long bt = idx / CH;
    int t = (int)(bt % T);
    const float4 wv = *reinterpret_cast<const float4*>(cw + (size_t)c * 4);
    const float* ip = Cp + (size_t)bt * CS_ + col0 + c;
    float s = ip[0] * wv.w;
    if (t >= 1) s += ip[-(long)CS_] * wv.z;
    if (t >= 2) s += ip[-2L * CS_] * wv.y;
    if (t >= 3) s += ip[-3L * CS_] * wv.x;
    out[idx] = s * sigmoidf_(s);
}

__global__ void decay_kernel(const float* __restrict__ graw, const float* __restrict__ dt_bias,
                             const float* __restrict__ A_log, float* __restrict__ dec, long total)
{
    long idx = (long)blockIdx.x * blockDim.x + threadIdx.x;
    if (idx >= total) return;
    int ch = (int)(idx & 2047);
    int h = ch >> 7;
    float x = graw[idx] + dt_bias[ch];
    dec[idx] = expf(-expf(A_log[h]) * softplusf_(x));
}

__global__ void beta_kernel(const float* __restrict__ Cp, float* __restrict__ out, long total)
{
    long idx = (long)blockIdx.x * blockDim.x + threadIdx.x;
    if (idx >= total) return;
    long bt = idx >> 6; int c = (int)(idx & 63);
    out[idx] = sigmoidf_(Cp[bt * CS_ + COL_B + c]);
}

// ----------------- delta-rule microscan (packed f32x2 FFMA2) ---------------
__global__ void __launch_bounds__(128, 1) scan_kernel(
    const float* __restrict__ qp, const float* __restrict__ kp,
    const float* __restrict__ vp, const float* __restrict__ dec,
    const float* __restrict__ beta,
    const float* __restrict__ dt_bias, const float* __restrict__ A_log,
    const float* __restrict__ micro_logits,
    float* __restrict__ o_mix, int T)
{
    const int split = blockIdx.x;
    const int h = blockIdx.y;
    const int b = blockIdx.z;
    const int tid = threadIdx.x;
    const int w = tid >> 5;
    const int c = tid & 31;
    const int vcol = split * 32 + c;

    __shared__ __align__(8) float sq[128], sdec[128], sk[512], sv[512];
    __shared__ float red[2][128], ored[128], sb4[4];

    const float A = expf(A_log[h]);
    u64 sdf2[16], swm2[4];
#pragma unroll
    for (int i = 0; i < 16; i++) {
        int d0 = w * 32 + 2 * i;
        float f0 = expf(-A * softplusf_(-10000.0f + dt_bias[h * 128 + d0]));
        float f1 = expf(-A * softplusf_(-10000.0f + dt_bias[h * 128 + d0 + 1]));
        sdf2[i] = pk2(f0, f1);
    }
    {
        float m0 = micro_logits[h * 4 + 0], m1 = micro_logits[h * 4 + 1];
        float m2 = micro_logits[h * 4 + 2], m3 = micro_logits[h * 4 + 3];
        float mx = fmaxf(fmaxf(m0, m1), fmaxf(m2, m3));
        float e0 = expf(m0 - mx), e1 = expf(m1 - mx), e2 = expf(m2 - mx), e3 = expf(m3 - mx);
        float inv = 1.f / (e0 + e1 + e2 + e3);
        swm2[0] = pk2(e0 * inv, e0 * inv); swm2[1] = pk2(e1 * inv, e1 * inv);
        swm2[2] = pk2(e2 * inv, e2 * inv); swm2[3] = pk2(e3 * inv, e3 * inv);
    }

    u64 S2[16];
#pragma unroll
    for (int i = 0; i < 16; i++) S2[i] = pk2(0.f, 0.f);

    {
        size_t base0 = ((size_t)(b * T) * H_ + h);
        size_t q0 = base0 * 128, k0 = base0 * 512;
#pragma unroll
        for (int i = 0; i < 5; i++) {
            int fl = tid + i * 128;
            const float2* src;
            float2* dst;
            if (fl < 64)       { src = (const float2*)(qp  + q0) + fl;        dst = (float2*)sq   + fl; }
            else if (fl < 128) { src = (const float2*)(dec + q0) + (fl - 64); dst = (float2*)sdec + (fl - 64); }
            else if (fl < 384) { src = (const float2*)(kp  + k0) + (fl - 128);dst = (float2*)sk   + (fl - 128); }
            else               { src = (const float2*)(vp  + k0) + (fl - 384);dst = (float2*)sv   + (fl - 384); }
            *dst = *src;
        }
        if (tid < 4) sb4[tid] = beta[base0 * 4 + tid];
    }
    __syncthreads();

    for (int t = 0; t < T; t++) {
        float2 pf[5]; float pfb = 0.f;
        {
            int tn = (t + 1 < T) ? (t + 1) : t;
            size_t basen = ((size_t)(b * T + tn) * H_ + h);
            size_t qn = basen * 128, kn = basen * 512;
#pragma unroll
            for (int i = 0; i < 5; i++) {
                int fl = tid + i * 128;
                const float2* src;
                if (fl < 64)       src = (const float2*)(qp  + qn) + fl;
                else if (fl < 128) src = (const float2*)(dec + qn) + (fl - 64);
                else if (fl < 384) src = (const float2*)(kp  + kn) + (fl - 128);
                else               src = (const float2*)(vp  + kn) + (fl - 384);
                pf[i] = *src;
            }
            if (tid < 4) pfb = beta[basen * 4 + tid];
        }

        u64 q2[16];
        {
            const float2* qsp = (const float2*)sq + w * 16;
#pragma unroll
            for (int i = 0; i < 16; i++) { float2 v = qsp[i]; q2[i] = pk2(v.x, v.y); }
        }

        u64 oacc2 = pk2(0.f, 0.f);
#pragma unroll
        for (int j = 0; j < 4; j++) {
            const float2* ksp = (const float2*)(sk + j * 128) + w * 16;
            u64 k2[16];
#pragma unroll
            for (int i = 0; i < 16; i++) { float2 v = ksp[i]; k2[i] = pk2(v.x, v.y); }

            u64 ua = pk2(0.f, 0.f), ub = pk2(0.f, 0.f);
            if (j == 0) {
                const float2* dsp = (const float2*)sdec + w * 16;
#pragma unroll
                for (int i = 0; i < 16; i++) {
                    float2 dv = dsp[i];
                    S2[i] = f2mul(S2[i], pk2(dv.x, dv.y));
                    if (i & 1) ub = f2fma(k2[i], S2[i], ub);
                    else       ua = f2fma(k2[i], S2[i], ua);
                }
            } else {
#pragma unroll
                for (int i = 0; i < 16; i++) {
                    S2[i] = f2mul(S2[i], sdf2[i]);
                    if (i & 1) ub = f2fma(k2[i], S2[i], ub);
                    else       ua = f2fma(k2[i], S2[i], ua);
                }
            }
            float ux, uy; upk2(f2add(ua, ub), ux, uy);
            red[j & 1][tid] = ux + uy;
            __syncthreads();
            float u = red[j & 1][c] + red[j & 1][32 + c] + red[j & 1][64 + c] + red[j & 1][96 + c];
            float coef = sb4[j] * (sv[j * 128 + vcol] - u);
            u64 c2 = pk2(coef, coef);

            u64 da = pk2(0.f, 0.f), db = pk2(0.f, 0.f);
#pragma unroll
            for (int i = 0; i < 16; i++) {
                S2[i] = f2fma(c2, k2[i], S2[i]);
                if (i & 1) db = f2fma(q2[i], S2[i], db);
                else       da = f2fma(q2[i], S2[i], da);
            }
            oacc2 = f2fma(swm2[j], f2add(da, db), oacc2);
        }

        float ox, oy; upk2(oacc2, ox, oy);
        ored[tid] = ox + oy;
        __syncthreads();
        if (w == 0)
            o_mix[((size_t)(b * T + t) * H_ + h) * 128 + vcol] =
                ored[c] + ored[32 + c] + ored[64 + c] + ored[96 + c];
#pragma unroll
        for (int i = 0; i < 5; i++) {
            int fl = tid + i * 128;
            float2* dst;
            if (fl < 64)       dst = (float2*)sq   + fl;
            else if (fl < 128) dst = (float2*)sdec + (fl - 64);
            else if (fl < 384) dst = (float2*)sk   + (fl - 128);
            else               dst = (float2*)sv   + (fl - 384);
            *dst = pf[i];
        }
        if (tid < 4) sb4[tid] = pfb;
        __syncthreads();
    }
}

// ------- output norm * gate -> fp16 (feeds o_proj GEMM directly) -----------
__global__ void post_kernel(const float* __restrict__ omix, const float* __restrict__ gate,
                            const float* __restrict__ onw, __half* __restrict__ ofin)
{
    size_t row = blockIdx.x;
    int v = threadIdx.x;
    float o = omix[row * 128 + v];
    float s = o * o;
#pragma unroll
    for (int off = 16; off > 0; off >>= 1) s += __shfl_xor_sync(0xffffffffu, s, off);
    __shared__ float ws[4];
    if ((v & 31) == 0) ws[v >> 5] = s;
    __syncthreads();
    float mean = (ws[0] + ws[1] + ws[2] + ws[3]) * (1.f / 128.f);
    float r = o * rsqrtf(mean + 1e-5f) * onw[v] * sigmoidf_(gate[row * 128 + v]);
    ofin[row * 128 + v] = __float2half_rn(r);
}

// ---------------------------------------------------------------------------
extern "C" void kernel_launch(void* const* d_in, const int* in_sizes, int n_in,
                              void* d_out, int out_size)
{
    const float* x       = (const float*)d_in[0];
    const float* q_proj  = (const float*)d_in[1];
    const float* k_proj  = (const float*)d_in[2];
    const float* v_proj  = (const float*)d_in[3];
    const float* q_convw = (const float*)d_in[4];
    const float* k_convw = (const float*)d_in[5];
    const float* v_convw = (const float*)d_in[6];
    const float* f1_w    = (const float*)d_in[7];
    const float* f2_w    = (const float*)d_in[8];
    const float* b_proj  = (const float*)d_in[9];
    const float* micro   = (const float*)d_in[10];
    const float* A_log   = (const float*)d_in[11];
    const float* dt_bias = (const float*)d_in[12];
    const float* g1_w    = (const float*)d_in[13];
    const float* g2_w    = (const float*)d_in[14];
    const float* g2_b    = (const float*)d_in[15];
    const float* o_normw = (const float*)d_in[16];
    const float* o_proj  = (const float*)d_in[17];
    float* out = (float*)d_out;

    const int T = T_;
    const int BT = in_sizes[0] / HID_;
    const int B = BT / T;

    cudaFuncSetAttribute(tgemm_kernel, cudaFuncAttributeMaxDynamicSharedMemorySize, TG_SMEM);

    float *cproj, *graw, *gate, *qb, *kb, *vb, *decb, *betab, *omix;
    cudaGetSymbolAddress((void**)&cproj, g_cproj);
    cudaGetSymbolAddress((void**)&graw,  g_graw);
    cudaGetSymbolAddress((void**)&gate,  g_gate);
    cudaGetSymbolAddress((void**)&qb,    g_qb);
    cudaGetSymbolAddress((void**)&kb,    g_kb);
    cudaGetSymbolAddress((void**)&vb,    g_vb);
    cudaGetSymbolAddress((void**)&decb,  g_dec);
    cudaGetSymbolAddress((void**)&betab, g_beta);
    cudaGetSymbolAddress((void**)&omix,  g_omix);

    __half *combh, *combl, *f2h, *f2l, *g2h, *g2l, *woh, *wol, *xh, *f1g1h, *aofh;
    cudaGetSymbolAddress((void**)&combh, g_combh);
    cudaGetSymbolAddress((void**)&combl, g_combl);
    cudaGetSymbolAddress((void**)&f2h,   g_wf2h);
    cudaGetSymbolAddress((void**)&f2l,   g_wf2l);
    cudaGetSymbolAddress((void**)&g2h,   g_wg2h);
    cudaGetSymbolAddress((void**)&g2l,   g_wg2l);
    cudaGetSymbolAddress((void**)&woh,   g_woh);
    cudaGetSymbolAddress((void**)&wol,   g_wol);
    cudaGetSymbolAddress((void**)&xh,    g_xh);
    cudaGetSymbolAddress((void**)&f1g1h, g_f1g1h);
    cudaGetSymbolAddress((void**)&aofh,  g_aofh);

    auto g4 = [](long n4) { return (unsigned)((n4 + 255) / 256); };

    splitw_kernel<<<g4((long)KD_  * HID_ / 4), 256>>>(q_proj, combh,                combl,                (long)KD_  * HID_ / 4);
    splitw_kernel<<<g4((long)KDR_ * HID_ / 4), 256>>>(k_proj, combh + (long)COL_K  * HID_, combl + (long)COL_K  * HID_, (long)KDR_ * HID_ / 4);
    splitw_kernel<<<g4((long)VDR_ * HID_ / 4), 256>>>(v_proj, combh + (long)COL_V  * HID_, combl + (long)COL_V  * HID_, (long)VDR_ * HID_ / 4);
    splitw_kernel<<<g4((long)64   * HID_ / 4), 256>>>(b_proj, combh + (long)COL_B  * HID_, combl + (long)COL_B  * HID_, (long)64   * HID_ / 4);
    splitw_kernel<<<g4((long)128  * HID_ / 4), 256>>>(f1_w,   combh + (long)COL_F1 * HID_, combl + (long)COL_F1 * HID_, (long)128  * HID_ / 4);
    splitw_kernel<<<g4((long)128  * HID_ / 4), 256>>>(g1_w,   combh + (long)(COL_F1 + 128) * HID_, combl + (long)(COL_F1 + 128) * HID_, (long)128 * HID_ / 4);
    splitw_kernel<<<g4((long)KD_ * 128 / 4),  256>>>(f2_w, f2h, f2l, (long)KD_ * 128 / 4);
    splitw_kernel<<<g4((long)KD_ * 128 / 4),  256>>>(g2_w, g2h, g2l, (long)KD_ * 128 / 4);
    splitw_kernel<<<g4((long)HID_ * KD_ / 4), 256>>>(o_proj, woh, wol, (long)HID_ * KD_ / 4);
    cvt16_kernel<<<g4((long)BT * HID_ / 4), 256>>>(x, xh, (long)BT * HID_ / 4);

    auto tg = [&](const __half* a, const __half* wh, const __half* wl,
                  float* C, const float* bias, int M, int N, int K, int lda) {
        dim3 grid((unsigned)(M / TBM), (unsigned)((N + TBN - 1) / TBN));  // M fast
        tgemm_kernel<<<grid, 256, TG_SMEM>>>(a, wh, wl, C, bias, M, N, K, lda);
    };

    // merged projection GEMM (q|k|v|b|f1|g1)
    tg(xh, combh, combl, cproj, nullptr, BT, CS_, HID_, HID_);

    // low-rank expansions off f1/g1 (K=128)
    cvt_f1g1_kernel<<<g4((long)BT * 256), 256>>>(cproj, f1g1h, (long)BT * 256);
    tg(f1g1h,       f2h, f2l, graw, nullptr, BT, KD_, 128, 256);
    tg(f1g1h + 128, g2h, g2l, gate, g2_b,    BT, KD_, 128, 256);

    // conv+silu(+l2norm) from merged proj
    convnorm_kernel<<<(unsigned)(BT * (KD_ >> 7)),  128>>>(cproj, q_convw, qb, COL_Q, KD_,  0.08838834764831843f, T);
    convnorm_kernel<<<(unsigned)(BT * (KDR_ >> 7)), 128>>>(cproj, k_convw, kb, COL_K, KDR_, 1.0f, T);
    long nv = (long)BT * VDR_;
    conv_silu_kernel<<<(unsigned)((nv + 255) / 256), 256>>>(cproj, v_convw, vb, COL_V, VDR_, nv, T);

    long nq = (long)BT * KD_;
    decay_kernel<<<(unsigned)((nq + 255) / 256), 256>>>(graw, dt_bias, A_log, decb, nq);
    long nb = (long)BT * 64;
    beta_kernel<<<(unsigned)((nb + 255) / 256), 256>>>(cproj, betab, nb);

    // sequential microscan (packed f32x2)
    dim3 sgrid(4, H_, (unsigned)B);
    scan_kernel<<<sgrid, 128>>>(qb, kb, vb, decb, betab, dt_bias, A_log, micro, omix, T);

    // output norm + gate -> fp16, then o_proj
    post_kernel<<<(unsigned)(BT * H_), 128>>>(omix, gate, o_normw, aofh);
    tg(aofh, woh, wol, out, nullptr, BT, HID_, KD_, KD_);
}